// round 3
// baseline (speedup 1.0000x reference)
#include <cuda_runtime.h>
#include <cuda_bf16.h>
#include <cstdint>

// ---------------- problem constants (fixed by dataset) ----------------
#define NNODES 100000
#define NEDGES 1600000
#define DH 128           // feature dim (D == H)
#define NG 512           // num graphs
#define NL 5             // total reps (input + 4 layers)
#define NLG 4            // GIN layers
#define OO 64            // output dim
#define BN_EPS 1e-5f

// ---------------- static device scratch (no allocations allowed) ------
__device__ float g_hidden[NLG][(size_t)NNODES * DH];  // h1..h4
__device__ float g_pooled[(size_t)NNODES * DH];
__device__ float g_y1[(size_t)NNODES * DH];
__device__ float g_z[(size_t)NNODES * DH];
__device__ int   g_deg[NNODES];
__device__ int   g_off[NNODES + 1];
__device__ int   g_cursor[NNODES];
__device__ int   g_srcs[NEDGES];
__device__ int   g_gstart[NG + 1];
__device__ float g_stats[NLG][2][2 * DH];   // [layer][stage][sum(128)|sumsq(128)]
__device__ float g_ph[NL][NG * DH];         // per-graph pooled reps
// bf16 hi/lo split weights, transposed to [n][k]: mats 0..3 = W1[l], 4..7 = W2[l]
__device__ __nv_bfloat16 g_whi[8][DH * DH];
__device__ __nv_bfloat16 g_wlo[8][DH * DH];

// ---------------- helpers ----------------------------------------------
__device__ __forceinline__ uint32_t smem_u32(const void* p) {
    uint32_t a;
    asm("{ .reg .u64 t; cvta.to.shared.u64 t, %1; cvt.u32.u64 %0, t; }"
        : "=r"(a) : "l"(p));
    return a;
}

__device__ __forceinline__ void ldx4(uint32_t* r, uint32_t addr) {
    asm volatile("ldmatrix.sync.aligned.m8n8.x4.shared.b16 {%0,%1,%2,%3}, [%4];"
                 : "=r"(r[0]), "=r"(r[1]), "=r"(r[2]), "=r"(r[3]) : "r"(addr));
}

__device__ __forceinline__ void mma16816(float* c, const uint32_t* a,
                                         uint32_t b0, uint32_t b1) {
    asm volatile(
        "mma.sync.aligned.m16n8k16.row.col.f32.bf16.bf16.f32 "
        "{%0,%1,%2,%3}, {%4,%5,%6,%7}, {%8,%9}, {%0,%1,%2,%3};"
        : "+f"(c[0]), "+f"(c[1]), "+f"(c[2]), "+f"(c[3])
        : "r"(a[0]), "r"(a[1]), "r"(a[2]), "r"(a[3]), "r"(b0), "r"(b1));
}

// smem tile geometry: 128 rows x 136 bf16 (272B rows -> conflict-free ldmatrix)
#define LDT 136
#define TILE_B (128 * LDT * 2)           // 34816 bytes per matrix
#define SMEM_BYTES (4 * TILE_B + 4 * 128 * 4)

// ---------------- small utility kernels --------------------------------
__global__ void zero_kernel(int n_nodes) {
    int i = blockIdx.x * blockDim.x + threadIdx.x;
    if (i < n_nodes) g_deg[i] = 0;
    if (i < NLG * 2 * 2 * DH) ((float*)g_stats)[i] = 0.0f;
}

__global__ void hist_kernel(const int* __restrict__ dst, int E) {
    int i = blockIdx.x * blockDim.x + threadIdx.x;
    if (i < E) atomicAdd(&g_deg[dst[i]], 1);
}

__global__ void scan_kernel(int n) {
    __shared__ int warpsum[32];
    __shared__ int carry_s;
    int tid = threadIdx.x, lane = tid & 31, wid = tid >> 5;
    if (tid == 0) carry_s = 0;
    __syncthreads();
    for (int base = 0; base < n; base += 1024) {
        int i = base + tid;
        int v = (i < n) ? g_deg[i] : 0;
        int xv = v;
        #pragma unroll
        for (int o = 1; o < 32; o <<= 1) {
            int t = __shfl_up_sync(0xffffffffu, xv, o);
            if (lane >= o) xv += t;
        }
        if (lane == 31) warpsum[wid] = xv;
        __syncthreads();
        if (wid == 0) {
            int w = warpsum[lane];
            int yv = w;
            #pragma unroll
            for (int o = 1; o < 32; o <<= 1) {
                int t = __shfl_up_sync(0xffffffffu, yv, o);
                if (lane >= o) yv += t;
            }
            warpsum[lane] = yv - w;
        }
        __syncthreads();
        int excl = carry_s + warpsum[wid] + xv - v;
        if (i < n) { g_off[i] = excl; g_cursor[i] = excl; }
        __syncthreads();
        if (tid == 1023) carry_s += warpsum[31] + xv;
        __syncthreads();
    }
    if (tid == 0) g_off[n] = carry_s;
}

__global__ void scatter_kernel(const int* __restrict__ src,
                               const int* __restrict__ dst, int E) {
    int i = blockIdx.x * blockDim.x + threadIdx.x;
    if (i < E) {
        int p = atomicAdd(&g_cursor[dst[i]], 1);
        g_srcs[p] = src[i];
    }
}

__global__ void gbounds_kernel(const int* __restrict__ gid, int n) {
    int i = blockIdx.x * blockDim.x + threadIdx.x;
    if (i > n) return;
    if (i == 0) {
        int b = gid[0];
        for (int g = 0; g <= b; ++g) g_gstart[g] = 0;
    } else if (i == n) {
        int a = gid[n - 1];
        for (int g = a + 1; g <= NG; ++g) g_gstart[g] = n;
    } else {
        int a = gid[i - 1], b = gid[i];
        for (int g = a + 1; g <= b; ++g) g_gstart[g] = i;
    }
}

// weight convert: W[k][n] fp32 -> [n][k] bf16 hi/lo (mats 0-3: W1, 4-7: W2)
__global__ void wconv_kernel(const float* __restrict__ W1,
                             const float* __restrict__ W2) {
    int i = blockIdx.x * blockDim.x + threadIdx.x;
    if (i >= 8 * DH * DH) return;
    int mat = i >> 14, r = i & 16383;
    int n = r >> 7, k = r & 127;
    const float* src = (mat < 4) ? (W1 + ((size_t)mat << 14))
                                 : (W2 + ((size_t)(mat - 4) << 14));
    float v = src[k * DH + n];
    __nv_bfloat16 hi = __float2bfloat16(v);
    __nv_bfloat16 lo = __float2bfloat16(v - __bfloat162float(hi));
    g_whi[mat][r] = hi;
    g_wlo[mat][r] = lo;
}

// ---------------- aggregation: warp per node, CSR gather ---------------
__global__ void agg_kernel(const float* __restrict__ h,
                           const float* __restrict__ eps, int l, int n) {
    int w = (blockIdx.x * blockDim.x + threadIdx.x) >> 5;
    if (w >= n) return;
    int lane = threadIdx.x & 31;
    float onepe = 1.0f + __ldg(&eps[l]);
    const float4* hv = (const float4*)h;
    float4 acc = __ldg(&hv[(size_t)w * 32 + lane]);
    acc.x *= onepe; acc.y *= onepe; acc.z *= onepe; acc.w *= onepe;
    int s = g_off[w], e = g_off[w + 1];
    int j = s;
    for (; j + 4 <= e; j += 4) {
        int s0 = g_srcs[j], s1 = g_srcs[j + 1], s2 = g_srcs[j + 2], s3 = g_srcs[j + 3];
        float4 v0 = __ldg(&hv[(size_t)s0 * 32 + lane]);
        float4 v1 = __ldg(&hv[(size_t)s1 * 32 + lane]);
        float4 v2 = __ldg(&hv[(size_t)s2 * 32 + lane]);
        float4 v3 = __ldg(&hv[(size_t)s3 * 32 + lane]);
        acc.x += (v0.x + v1.x) + (v2.x + v3.x);
        acc.y += (v0.y + v1.y) + (v2.y + v3.y);
        acc.z += (v0.z + v1.z) + (v2.z + v3.z);
        acc.w += (v0.w + v1.w) + (v2.w + v3.w);
    }
    for (; j < e; ++j) {
        int s0 = g_srcs[j];
        float4 v0 = __ldg(&hv[(size_t)s0 * 32 + lane]);
        acc.x += v0.x; acc.y += v0.y; acc.z += v0.z; acc.w += v0.w;
    }
    ((float4*)g_pooled)[(size_t)w * 32 + lane] = acc;
}

// ---------------- mma.sync GEMM with bf16 hi/lo split ------------------
// C[M,128] = f(A)[M,128] @ Wt^T + bias, f = identity or relu(bn) via g_stats[l][0].
// Accumulates column sum/sumsq into g_stats[l][stage].
template <bool PRE_BN>
__global__ void __launch_bounds__(512)
gemm_mma(const float* __restrict__ A,
         const __nv_bfloat16* __restrict__ Bhi, const __nv_bfloat16* __restrict__ Blo,
         const float* __restrict__ bias,
         const float* __restrict__ gamma, const float* __restrict__ beta,
         float* __restrict__ C, int l, int M) {
    extern __shared__ char sb[];
    __nv_bfloat16* sAhi = (__nv_bfloat16*)sb;
    __nv_bfloat16* sAlo = sAhi + 128 * LDT;
    __nv_bfloat16* sBhi = sAlo + 128 * LDT;
    __nv_bfloat16* sBlo = sBhi + 128 * LDT;
    float* s_scale = (float*)(sBlo + 128 * LDT);
    float* s_shift = s_scale + 128;
    float* s_sum   = s_shift + 128;
    float* s_sq    = s_sum + 128;

    int tid = threadIdx.x;
    if (tid < 128) { s_sum[tid] = 0.0f; s_sq[tid] = 0.0f; }
    if (PRE_BN && tid < 128) {
        float inv = 1.0f / (float)M;
        float m = g_stats[l][0][tid] * inv;
        float v = g_stats[l][0][128 + tid] * inv - m * m;
        float s = __ldg(&gamma[tid]) * rsqrtf(v + BN_EPS);
        s_scale[tid] = s;
        s_shift[tid] = __ldg(&beta[tid]) - m * s;
    }
    if (PRE_BN) __syncthreads();   // s_scale ready before A conversion

    // ---- stage B hi/lo ([n][k] bf16) into smem ----
    const uint32_t* bh = (const uint32_t*)Bhi;
    const uint32_t* bl = (const uint32_t*)Blo;
    #pragma unroll
    for (int it = 0; it < 16; ++it) {
        int i = tid + it * 512;              // 8192 u32
        int n = i >> 6, kp = (i & 63);
        int d = n * LDT + kp * 2;
        *(uint32_t*)&sBhi[d] = bh[i];
        *(uint32_t*)&sBlo[d] = bl[i];
    }

    // ---- stage A tile (fp32 -> optional BN/ReLU -> bf16 hi/lo) ----
    int row0 = blockIdx.x * 128;
    const float4* A4 = (const float4*)(A + (size_t)row0 * DH);
    #pragma unroll
    for (int it = 0; it < 8; ++it) {
        int idx = tid + it * 512;            // 4096 float4
        int r = idx >> 5, c4 = (idx & 31) * 4;
        float4 v = make_float4(0.f, 0.f, 0.f, 0.f);
        if (row0 + r < M) v = A4[idx];
        if (PRE_BN) {
            v.x = fmaxf(fmaf(v.x, s_scale[c4 + 0], s_shift[c4 + 0]), 0.0f);
            v.y = fmaxf(fmaf(v.y, s_scale[c4 + 1], s_shift[c4 + 1]), 0.0f);
            v.z = fmaxf(fmaf(v.z, s_scale[c4 + 2], s_shift[c4 + 2]), 0.0f);
            v.w = fmaxf(fmaf(v.w, s_scale[c4 + 3], s_shift[c4 + 3]), 0.0f);
        }
        __nv_bfloat16 hx = __float2bfloat16(v.x), hy = __float2bfloat16(v.y);
        __nv_bfloat16 hz = __float2bfloat16(v.z), hw = __float2bfloat16(v.w);
        uint2 hi2, lo2;
        {
            __nv_bfloat162 t01, t23;
            t01.x = hx; t01.y = hy; t23.x = hz; t23.y = hw;
            hi2.x = *(uint32_t*)&t01; hi2.y = *(uint32_t*)&t23;
            t01.x = __float2bfloat16(v.x - __bfloat162float(hx));
            t01.y = __float2bfloat16(v.y - __bfloat162float(hy));
            t23.x = __float2bfloat16(v.z - __bfloat162float(hz));
            t23.y = __float2bfloat16(v.w - __bfloat162float(hw));
            lo2.x = *(uint32_t*)&t01; lo2.y = *(uint32_t*)&t23;
        }
        int d = r * LDT + c4;
        *(uint2*)&sAhi[d] = hi2;
        *(uint2*)&sAlo[d] = lo2;
    }
    __syncthreads();

    // ---- warp-tile mma: 4x4 warps, each 32(m) x 32(n) ----
    int w = tid >> 5, lane = tid & 31;
    int mw = (w >> 2) * 32, nw = (w & 3) * 32;
    uint32_t base = smem_u32(sb);
    // per-thread ldmatrix offsets (bytes)
    uint32_t aoff = ((mw + (lane & 15)) * LDT + ((lane >> 4) * 8)) * 2;
    uint32_t boff = ((nw + (lane & 7) + ((lane >> 4) << 3)) * LDT
                     + (((lane >> 3) & 1) * 8)) * 2;

    float acc[2][4][4];
    #pragma unroll
    for (int i = 0; i < 2; ++i)
        #pragma unroll
        for (int j = 0; j < 4; ++j)
            #pragma unroll
            for (int k = 0; k < 4; ++k) acc[i][j][k] = 0.0f;

    const uint32_t aT[3] = {0u, (uint32_t)TILE_B, 0u};                 // Ahi, Alo, Ahi
    const uint32_t bT[3] = {2u * TILE_B, 2u * TILE_B, 3u * TILE_B};    // Bhi, Bhi, Blo
    #pragma unroll
    for (int t = 0; t < 3; ++t) {
        uint32_t ab = base + aT[t] + aoff;
        uint32_t bb = base + bT[t] + boff;
        #pragma unroll
        for (int ks = 0; ks < 8; ++ks) {
            uint32_t a0[4], a1[4], b0[4], b1[4];
            ldx4(a0, ab + ks * 32);
            ldx4(a1, ab + 16 * LDT * 2 + ks * 32);
            ldx4(b0, bb + ks * 32);
            ldx4(b1, bb + 16 * LDT * 2 + ks * 32);
            mma16816(acc[0][0], a0, b0[0], b0[1]);
            mma16816(acc[0][1], a0, b0[2], b0[3]);
            mma16816(acc[0][2], a0, b1[0], b1[1]);
            mma16816(acc[0][3], a0, b1[2], b1[3]);
            mma16816(acc[1][0], a1, b0[0], b0[1]);
            mma16816(acc[1][1], a1, b0[2], b0[3]);
            mma16816(acc[1][2], a1, b1[0], b1[1]);
            mma16816(acc[1][3], a1, b1[2], b1[3]);
        }
    }

    // ---- epilogue: bias, direct store, column stats ----
    float csum[8], csq[8];
    #pragma unroll
    for (int i = 0; i < 8; ++i) { csum[i] = 0.0f; csq[i] = 0.0f; }
    #pragma unroll
    for (int nf = 0; nf < 4; ++nf) {
        int col = nw + nf * 8 + (lane & 3) * 2;
        float bx = __ldg(&bias[col]), by = __ldg(&bias[col + 1]);
        #pragma unroll
        for (int mf = 0; mf < 2; ++mf) {
            int r0 = row0 + mw + mf * 16 + (lane >> 2);
            float v0 = acc[mf][nf][0] + bx, v1 = acc[mf][nf][1] + by;
            float v2 = acc[mf][nf][2] + bx, v3 = acc[mf][nf][3] + by;
            if (r0 < M) {
                *(float2*)&C[(size_t)r0 * DH + col] = make_float2(v0, v1);
                csum[nf * 2] += v0; csum[nf * 2 + 1] += v1;
                csq[nf * 2] += v0 * v0; csq[nf * 2 + 1] += v1 * v1;
            }
            if (r0 + 8 < M) {
                *(float2*)&C[(size_t)(r0 + 8) * DH + col] = make_float2(v2, v3);
                csum[nf * 2] += v2; csum[nf * 2 + 1] += v3;
                csq[nf * 2] += v2 * v2; csq[nf * 2 + 1] += v3 * v3;
            }
        }
    }
    #pragma unroll
    for (int nf = 0; nf < 4; ++nf) {
        int col = nw + nf * 8 + (lane & 3) * 2;
        atomicAdd(&s_sum[col], csum[nf * 2]);
        atomicAdd(&s_sum[col + 1], csum[nf * 2 + 1]);
        atomicAdd(&s_sq[col], csq[nf * 2]);
        atomicAdd(&s_sq[col + 1], csq[nf * 2 + 1]);
    }
    __syncthreads();
    const int stage = PRE_BN ? 1 : 0;
    if (tid < 128) {
        atomicAdd(&g_stats[l][stage][tid], s_sum[tid]);
        atomicAdd(&g_stats[l][stage][128 + tid], s_sq[tid]);
    }
}

// ---------------- outer BN + ReLU, writes hidden rep -------------------
__global__ void finish_kernel(const float* __restrict__ z,
                              const float* __restrict__ gamma,
                              const float* __restrict__ beta,
                              float* __restrict__ hout, int l, int M) {
    __shared__ float s_scale[128], s_shift[128];
    int tid = threadIdx.x;
    if (tid < 128) {
        float inv = 1.0f / (float)M;
        float m = g_stats[l][1][tid] * inv;
        float v = g_stats[l][1][128 + tid] * inv - m * m;
        float s = __ldg(&gamma[tid]) * rsqrtf(v + BN_EPS);
        s_scale[tid] = s;
        s_shift[tid] = __ldg(&beta[tid]) - m * s;
    }
    __syncthreads();
    int idx = blockIdx.x * blockDim.x + tid;  // float4 index
    if (idx < M * 32) {
        int c = (idx & 31) * 4;
        float4 v = ((const float4*)z)[idx];
        float4 o;
        o.x = fmaxf(fmaf(v.x, s_scale[c + 0], s_shift[c + 0]), 0.0f);
        o.y = fmaxf(fmaf(v.y, s_scale[c + 1], s_shift[c + 1]), 0.0f);
        o.z = fmaxf(fmaf(v.z, s_scale[c + 2], s_shift[c + 2]), 0.0f);
        o.w = fmaxf(fmaf(v.w, s_scale[c + 3], s_shift[c + 3]), 0.0f);
        ((float4*)hout)[idx] = o;
    }
}

// ---------------- per-graph segmented pooling of all 5 reps ------------
__global__ void pool_kernel(const float* __restrict__ x) {
    int g = blockIdx.x, l = blockIdx.y, c = threadIdx.x;
    const float* h = (l == 0) ? x : &g_hidden[l - 1][0];
    int s = g_gstart[g], e = g_gstart[g + 1];
    float acc = 0.0f;
    int r = s;
    for (; r + 4 <= e; r += 4) {
        acc += __ldg(&h[(size_t)(r + 0) * DH + c]);
        acc += __ldg(&h[(size_t)(r + 1) * DH + c]);
        acc += __ldg(&h[(size_t)(r + 2) * DH + c]);
        acc += __ldg(&h[(size_t)(r + 3) * DH + c]);
    }
    for (; r < e; ++r) acc += __ldg(&h[(size_t)r * DH + c]);
    g_ph[l][g * DH + c] = acc;
}

// ---------------- final score: 512 x 64 --------------------------------
__global__ void score_kernel(const float* __restrict__ Wp,
                             const float* __restrict__ bp,
                             float* __restrict__ out) {
    int g = blockIdx.x;
    __shared__ float sph[NL * DH];
    for (int i = threadIdx.x; i < NL * DH; i += blockDim.x) {
        int l = i / DH, c = i % DH;
        sph[i] = g_ph[l][g * DH + c];
    }
    __syncthreads();
    int o = threadIdx.x;  // 64 threads
    float acc = 0.0f;
    for (int l = 0; l < NL; ++l) {
        acc += __ldg(&bp[l * OO + o]);
        const float* Wl = Wp + (size_t)l * DH * OO;
        #pragma unroll 4
        for (int c = 0; c < DH; ++c)
            acc = fmaf(sph[l * DH + c], __ldg(&Wl[c * OO + o]), acc);
    }
    out[g * OO + o] = acc;
}

// ---------------- launcher ---------------------------------------------
extern "C" void kernel_launch(void* const* d_in, const int* in_sizes, int n_in,
                              void* d_out, int out_size) {
    const float* x   = (const float*)d_in[0];
    const int*   src = (const int*)d_in[1];
    const int*   dst = (const int*)d_in[2];
    const int*   gid = (const int*)d_in[3];
    const float* eps = (const float*)d_in[5];
    const float* W1  = (const float*)d_in[6];
    const float* b1  = (const float*)d_in[7];
    const float* gm  = (const float*)d_in[8];
    const float* bm  = (const float*)d_in[9];
    const float* W2  = (const float*)d_in[10];
    const float* b2  = (const float*)d_in[11];
    const float* go  = (const float*)d_in[12];
    const float* bo  = (const float*)d_in[13];
    const float* Wp  = (const float*)d_in[14];
    const float* bp  = (const float*)d_in[15];
    float* out = (float*)d_out;

    int N = in_sizes[0] / DH;   // 100000
    int E = in_sizes[1];        // 1600000

    float *pooled, *y1, *z, *hid;
    __nv_bfloat16 *whi, *wlo;
    cudaGetSymbolAddress((void**)&pooled, g_pooled);
    cudaGetSymbolAddress((void**)&y1, g_y1);
    cudaGetSymbolAddress((void**)&z, g_z);
    cudaGetSymbolAddress((void**)&hid, g_hidden);
    cudaGetSymbolAddress((void**)&whi, g_whi);
    cudaGetSymbolAddress((void**)&wlo, g_wlo);

    static bool attr_done = false;
    if (!attr_done) {
        cudaFuncSetAttribute(gemm_mma<false>,
                             cudaFuncAttributeMaxDynamicSharedMemorySize, SMEM_BYTES);
        cudaFuncSetAttribute(gemm_mma<true>,
                             cudaFuncAttributeMaxDynamicSharedMemorySize, SMEM_BYTES);
        attr_done = true;
    }

    zero_kernel<<<(N + 255) / 256, 256>>>(N);
    hist_kernel<<<(E + 255) / 256, 256>>>(dst, E);
    scan_kernel<<<1, 1024>>>(N);
    scatter_kernel<<<(E + 255) / 256, 256>>>(src, dst, E);
    gbounds_kernel<<<(N + 1 + 255) / 256, 256>>>(gid, N);
    wconv_kernel<<<(8 * DH * DH + 255) / 256, 256>>>(W1, W2);

    int gemmGrid = (N + 127) / 128;
    int elemGrid = (N * 32 + 255) / 256;
    int aggGrid  = (N * 32 + 255) / 256;  // warp per node

    for (int l = 0; l < NLG; ++l) {
        const float* h = (l == 0) ? x : (hid + (size_t)(l - 1) * (size_t)N * DH);
        agg_kernel<<<aggGrid, 256>>>(h, eps, l, N);
        gemm_mma<false><<<gemmGrid, 512, SMEM_BYTES>>>(
            pooled, whi + (size_t)l * DH * DH, wlo + (size_t)l * DH * DH,
            b1 + l * DH, nullptr, nullptr, y1, l, N);
        gemm_mma<true><<<gemmGrid, 512, SMEM_BYTES>>>(
            y1, whi + (size_t)(4 + l) * DH * DH, wlo + (size_t)(4 + l) * DH * DH,
            b2 + l * DH, gm + l * DH, bm + l * DH, z, l, N);
        finish_kernel<<<elemGrid, 256>>>(z, go + l * DH, bo + l * DH,
                                         hid + (size_t)l * (size_t)N * DH, l, N);
    }

    dim3 pg(NG, NL);
    pool_kernel<<<pg, DH>>>(x);
    score_kernel<<<NG, 64>>>(Wp, bp, out);
}